// round 14
// baseline (speedup 1.0000x reference)
#include <cuda_runtime.h>
#include <cuda_fp16.h>
#include <cstdint>
#include <cstddef>

#define FEAT 128
#define NUM_BASES 4
#define NCT 5
#define MAX_NODES 100000
#define PROJ_STRIDE (NUM_BASES * FEAT)   // 512 halfs per node

typedef unsigned int u32;

// scratch: fp16 basis projections (102 MB, fits L2) + transposed fp16 weights
__device__ __half g_projh[(size_t)MAX_NODES * PROJ_STRIDE];
__device__ __half g_wth[NCT * FEAT * FEAT];   // [ct][n][k] = fp16(W_ct[k][n])

__device__ __forceinline__ void mma_f16(float* d, const u32* a, const u32* b) {
    asm("mma.sync.aligned.m16n8k16.row.col.f32.f16.f16.f32 "
        "{%0,%1,%2,%3}, {%4,%5,%6,%7}, {%8,%9}, {%0,%1,%2,%3};"
        : "+f"(d[0]), "+f"(d[1]), "+f"(d[2]), "+f"(d[3])
        : "r"(a[0]), "r"(a[1]), "r"(a[2]), "r"(a[3]), "r"(b[0]), "r"(b[1]));
}
__device__ __forceinline__ u32 smem_u32(const void* p) {
    u32 a;
    asm("{ .reg .u64 t; cvta.to.shared.u64 t, %1; cvt.u32.u64 %0, t; }" : "=r"(a) : "l"(p));
    return a;
}
__device__ __forceinline__ void ldsm4(u32& r0, u32& r1, u32& r2, u32& r3, u32 addr) {
    asm volatile("ldmatrix.sync.aligned.m8n8.x4.shared.b16 {%0,%1,%2,%3}, [%4];"
                 : "=r"(r0), "=r"(r1), "=r"(r2), "=r"(r3) : "r"(addr));
}
__device__ __forceinline__ void red_add_v4(float* ptr, float a, float b, float c, float d) {
    asm volatile("red.global.add.v4.f32 [%0], {%1, %2, %3, %4};"
                 :: "l"(ptr), "f"(a), "f"(b), "f"(c), "f"(d) : "memory");
}
__device__ __forceinline__ void cpa16(u32 dst, const void* src) {
    asm volatile("cp.async.ca.shared.global [%0], [%1], 16;" :: "r"(dst), "l"(src));
}
#define CPA_COMMIT() asm volatile("cp.async.commit_group;" ::: "memory")
#define CPA_WAIT(n)  asm volatile("cp.async.wait_group %0;" :: "n"(n) : "memory")

// ---------------- kernel 0: transpose weights into fp16 g_wth ----------------
__global__ void transpose_w_kernel(const float* __restrict__ weight,
                                   const float* __restrict__ root)
{
    __shared__ float tile[32][33];
    const int ct = blockIdx.z;
    const float* __restrict__ src = (ct < NUM_BASES) ? (weight + (size_t)ct * FEAT * FEAT)
                                                     : root;
    const int n0 = blockIdx.x * 32, k0 = blockIdx.y * 32;
    const int tx = threadIdx.x, ty = threadIdx.y;  // 32 x 8
#pragma unroll
    for (int j = 0; j < 32; j += 8)
        tile[ty + j][tx] = src[(size_t)(k0 + ty + j) * FEAT + n0 + tx];
    __syncthreads();
    __half* __restrict__ dst = g_wth + (size_t)ct * FEAT * FEAT;
#pragma unroll
    for (int j = 0; j < 32; j += 8)
        dst[(size_t)(n0 + ty + j) * FEAT + k0 + tx] = __float2half_rn(tile[tx][ty + j]);
}

// ---------------- kernel 1: fp16 mma GEMM, A-resident, 512 thr, 32x32 warp tile ----------------
// One block = 128 rows of h; loops ct = 0..4:
//   ct 0..3 -> g_projh[:, ct, :] (fp16),  ct 4 -> out = h@root + bias (fp32)
#define PADH 136                      // halfs per row (272 B; ldmatrix conflict-free)
#define TILE_H (128 * PADH)
#define SM_TOTALB (3 * TILE_H * 2)    // A + 2 B buffers = 104448 B
#define NT 512

__global__ void __launch_bounds__(NT, 2)
rgcn_gemm_mma_kernel(const float* __restrict__ h,
                     const float* __restrict__ bias,
                     float* __restrict__ out, int n_nodes)
{
    extern __shared__ __half smemh[];
    __half* As = smemh;

    const int tid  = threadIdx.x;
    const int lane = tid & 31;
    const int w    = tid >> 5;        // 0..15
    const int g    = lane >> 2;
    const int tig  = lane & 3;
    const int warp_m = w & 3;         // 4 warps in M: 32 rows each
    const int warp_n = w >> 2;        // 4 warps in N: 32 cols each

    const int row0 = blockIdx.x * 128;

    const int l_row = lane & 15;
    const int l_kd  = (lane >> 4) * 8;

    const u32 sA = smem_u32(As);
    const u32 sB0 = sA + TILE_H * 2;
    const u32 sB1 = sA + 2 * TILE_H * 2;

    // ---- A producer: load h rows once, convert to fp16 ----
#pragma unroll
    for (int i = 0; i < 8; i++) {
        const int v  = tid + i * NT;
        const int r  = v >> 5;          // 0..127
        const int c4 = (v & 31) * 4;    // 0..124
        float4 av = make_float4(0.f, 0.f, 0.f, 0.f);
        const int gr = row0 + r;
        if (gr < n_nodes)
            av = *(const float4*)(h + (size_t)gr * FEAT + c4);
        __half2 a01 = __floats2half2_rn(av.x, av.y);
        __half2 a23 = __floats2half2_rn(av.z, av.w);
        *(uint2*)(As + r * PADH + c4) = make_uint2(*(u32*)&a01, *(u32*)&a23);
    }

    // ---- B prefetch: full-K fp16 tile for ct via cp.async ----
    auto issue_b = [&](int ct, u32 sBdst) {
        const __half* __restrict__ src = g_wth + (size_t)ct * FEAT * FEAT;
#pragma unroll
        for (int i = 0; i < 4; i++) {
            const int v  = tid + i * NT;
            const int r  = v >> 4;          // 0..127
            const int c8 = (v & 15) * 8;    // 0..120 halfs
            cpa16(sBdst + (u32)((r * PADH + c8) * 2), src + (size_t)r * FEAT + c8);
        }
        CPA_COMMIT();
    };

    issue_b(0, sB0);

    float acc[2][4][4];
#pragma unroll
    for (int mi = 0; mi < 2; mi++)
#pragma unroll
        for (int j = 0; j < 4; j++)
#pragma unroll
            for (int c = 0; c < 4; c++) acc[mi][j][c] = 0.f;

#pragma unroll 1
    for (int ct = 0; ct < NCT; ct++) {
        if (ct + 1 < NCT) {
            issue_b(ct + 1, ((ct + 1) & 1) ? sB1 : sB0);
            CPA_WAIT(1);
        } else {
            CPA_WAIT(0);
        }
        __syncthreads();
        const u32 sB = (ct & 1) ? sB1 : sB0;

#pragma unroll
        for (int ks = 0; ks < 8; ks++) {
            const int kk = ks * 16;
            u32 af[2][4];
#pragma unroll
            for (int mi = 0; mi < 2; mi++) {
                const u32 off = (u32)(((warp_m * 32 + mi * 16 + l_row) * PADH
                                       + kk + l_kd) * 2);
                ldsm4(af[mi][0], af[mi][1], af[mi][2], af[mi][3], sA + off);
            }
            u32 bf[4][2];
            {
                // one x4 per 16 n-rows; warp covers 32 n-cols = 2 jp groups
#pragma unroll
                for (int jp = 0; jp < 2; jp++) {
                    const u32 off = (u32)(((warp_n * 32 + jp * 16 + l_row) * PADH
                                           + kk + l_kd) * 2);
                    u32 m0, m1, m2, m3;
                    ldsm4(m0, m1, m2, m3, sB + off);
                    bf[2 * jp][0] = m0;     bf[2 * jp][1] = m2;
                    bf[2 * jp + 1][0] = m1; bf[2 * jp + 1][1] = m3;
                }
            }
#pragma unroll
            for (int mi = 0; mi < 2; mi++)
#pragma unroll
                for (int j = 0; j < 4; j++)
                    mma_f16(acc[mi][j], af[mi], bf[j]);
        }
        __syncthreads();   // protect B buffer before refill at ct+2

        // ---- epilogue for this ct ----
#pragma unroll
        for (int mi = 0; mi < 2; mi++) {
#pragma unroll
            for (int half = 0; half < 2; half++) {
                const int grow = row0 + warp_m * 32 + mi * 16 + g + half * 8;
                if (grow < n_nodes) {
                    if (ct < NUM_BASES) {
                        __half* p = g_projh + (size_t)grow * PROJ_STRIDE + ct * FEAT
                                  + warp_n * 32 + 2 * tig;
#pragma unroll
                        for (int j = 0; j < 4; j++)
                            *(__half2*)(p + 8 * j) =
                                __floats2half2_rn(acc[mi][j][2 * half],
                                                  acc[mi][j][2 * half + 1]);
                    } else {
                        float* p = out + (size_t)grow * FEAT + warp_n * 32 + 2 * tig;
#pragma unroll
                        for (int j = 0; j < 4; j++) {
                            const float2 b =
                                *(const float2*)(bias + warp_n * 32 + 2 * tig + 8 * j);
                            *(float2*)(p + 8 * j) =
                                make_float2(acc[mi][j][2 * half] + b.x,
                                            acc[mi][j][2 * half + 1] + b.y);
                        }
                    }
                }
            }
        }
#pragma unroll
        for (int mi = 0; mi < 2; mi++)
#pragma unroll
            for (int j = 0; j < 4; j++)
#pragma unroll
                for (int c = 0; c < 4; c++) acc[mi][j][c] = 0.f;
    }
}

// ---------------- kernel 2: edge gather/combine/scatter (vector red) ----------------
__global__ void rgcn_edge_kernel(const float* __restrict__ w_comp,
                                 const int* __restrict__ src,
                                 const int* __restrict__ dst,
                                 const int* __restrict__ rel,
                                 float* __restrict__ out, int n_edges)
{
    const int warp = (blockIdx.x * blockDim.x + threadIdx.x) >> 5;
    const int lane = threadIdx.x & 31;
    if (warp >= n_edges) return;

    const int s = src[warp];
    const int d = dst[warp];
    const int r = rel[warp];
    const float4 c = *(const float4*)(w_comp + r * NUM_BASES);

    const uint2* __restrict__ p =
        (const uint2*)(g_projh + (size_t)s * PROJ_STRIDE) + lane;
    float m0 = 0.f, m1 = 0.f, m2 = 0.f, m3 = 0.f;
#pragma unroll
    for (int b = 0; b < 4; b++) {
        const float cb = (&c.x)[b];
        const uint2 raw = p[b * 32];
        const float2 v0 = __half22float2(*(const __half2*)&raw.x);
        const float2 v1 = __half22float2(*(const __half2*)&raw.y);
        m0 = fmaf(cb, v0.x, m0);
        m1 = fmaf(cb, v0.y, m1);
        m2 = fmaf(cb, v1.x, m2);
        m3 = fmaf(cb, v1.y, m3);
    }

    red_add_v4(out + (size_t)d * FEAT + 4 * lane, m0, m1, m2, m3);
}

__global__ void rgcn_relu_kernel(float* __restrict__ out, int n4)
{
    int i = blockIdx.x * blockDim.x + threadIdx.x;
    if (i < n4) {
        float4 v = ((float4*)out)[i];
        v.x = fmaxf(v.x, 0.f); v.y = fmaxf(v.y, 0.f);
        v.z = fmaxf(v.z, 0.f); v.w = fmaxf(v.w, 0.f);
        ((float4*)out)[i] = v;
    }
}

extern "C" void kernel_launch(void* const* d_in, const int* in_sizes, int n_in,
                              void* d_out, int out_size)
{
    const float* h      = (const float*)d_in[0];
    const float* weight = (const float*)d_in[1];
    const float* w_comp = (const float*)d_in[2];
    const float* root   = (const float*)d_in[3];
    const float* bias   = (const float*)d_in[4];
    const int*   src    = (const int*)d_in[5];
    const int*   dst    = (const int*)d_in[6];
    const int*   rel    = (const int*)d_in[7];

    const int n_nodes = in_sizes[0] / FEAT;
    const int n_edges = in_sizes[5];
    float* out = (float*)d_out;

    cudaFuncSetAttribute(rgcn_gemm_mma_kernel,
                         cudaFuncAttributeMaxDynamicSharedMemorySize, SM_TOTALB);

    // 0) transpose + fp16-convert weights (tiny)
    dim3 gt(4, 4, NCT);
    transpose_w_kernel<<<gt, dim3(32, 8)>>>(weight, root);

    // 1) fp16 GEMM, A resident, 512 threads, loop over 5 weight matrices
    rgcn_gemm_mma_kernel<<<(n_nodes + 127) / 128, NT, SM_TOTALB>>>(h, bias, out, n_nodes);

    // 2) edge combine + vector scatter-add
    int blocks_e = (n_edges + 7) / 8;
    rgcn_edge_kernel<<<blocks_e, 256>>>(w_comp, src, dst, rel, out, n_edges);

    // 3) ReLU
    int n4 = out_size / 4;
    rgcn_relu_kernel<<<(n4 + 255) / 256, 256>>>(out, n4);
}